// round 12
// baseline (speedup 1.0000x reference)
#include <cuda_runtime.h>
#include <cuda_bf16.h>

// ---- constexpr permutation of the per-layer CU block ----
__host__ __device__ constexpr int sig1(int k) {
    int b = (k >> 3) & 1, c = (k >> 2) & 1, d = (k >> 1) & 1, e = k & 1;
    if (b) c ^= 1;
    if (c) d ^= 1;
    if (d) e ^= 1;
    if (e) b ^= 1;
    return b * 8 + c * 4 + d * 2 + e;
}
__host__ __device__ constexpr int sigp(int k, int n) {
    for (int i = 0; i < n; i++) k = sig1(k);
    return k;
}
__host__ __device__ constexpr int isigp(int j, int n) {
    for (int k = 0; k < 16; k++)
        if (sigp(k, n) == j) return k;
    return 0;
}

// Runtime phase walk for basis state k through one layer's 4 CU gates.
// Target 1->0: -i*e = (s, -c); 0->1: -i*conj(e) = (-s, -c); e = e^{i th/2}.
__device__ __forceinline__ void cu_walk(int k, const float* th,
                                        float& pr, float& pi) {
    pr = 1.f; pi = 0.f;
    int b = (k >> 3) & 1, c = (k >> 2) & 1, d = (k >> 1) & 1, e = k & 1;
    float s, cc, fr, fi, nr, ni;
#define CUW(CTRL, TGT, IDX)                                   \
    if (CTRL) {                                               \
        __sincosf(0.5f * th[IDX], &s, &cc);                   \
        fr = (TGT) ? s : -s; fi = -cc;                        \
        nr = pr * fr - pi * fi; ni = pr * fi + pi * fr;       \
        pr = nr; pi = ni; TGT ^= 1;                           \
    }
    CUW(b, c, 0) CUW(c, d, 1) CUW(d, e, 2) CUW(e, b, 3)
#undef CUW
}

// Unnormalized RX (I - i*tau*X) on wire TB, both branches, perm sig^N.
template <int TB, int N>
__device__ __forceinline__ void rx_t(float (&sr)[32], float (&si)[32],
                                     float tau) {
#pragma unroll
    for (int p = 0; p < 16; p++) {
        const int lp = sigp(p, N);
        if (lp & TB) continue;
        const int q = isigp(lp | TB, N);
        {
            float t0r = sr[p], t0i = si[p], t1r = sr[q], t1i = si[q];
            sr[p] = fmaf(tau, t1i, t0r); si[p] = fmaf(-tau, t1r, t0i);
            sr[q] = fmaf(tau, t0i, t1r); si[q] = fmaf(-tau, t0r, t1i);
        }
        {
            float t0r = sr[p + 16], t0i = si[p + 16];
            float t1r = sr[q + 16], t1i = si[q + 16];
            sr[p + 16] = fmaf(tau, t1i, t0r); si[p + 16] = fmaf(-tau, t1r, t0i);
            sr[q + 16] = fmaf(tau, t0i, t1r); si[q + 16] = fmaf(-tau, t0r, t1i);
        }
    }
}

// Same, but on the lo 16 slots only (pre-fork shared state).
template <int TB, int N>
__device__ __forceinline__ void rx16_t(float (&sr)[32], float (&si)[32],
                                       float tau) {
#pragma unroll
    for (int p = 0; p < 16; p++) {
        const int lp = sigp(p, N);
        if (lp & TB) continue;
        const int q = isigp(lp | TB, N);
        float t0r = sr[p], t0i = si[p], t1r = sr[q], t1i = si[q];
        sr[p] = fmaf(tau, t1i, t0r); si[p] = fmaf(-tau, t1r, t0i);
        sr[q] = fmaf(tau, t0i, t1r); si[q] = fmaf(-tau, t0r, t1i);
    }
}

// Layer-1 CU block = per-slot phase multiply (perm handled by relabeling).
template <int N>
__device__ __forceinline__ void cu_tab(float (&sr)[32], float (&si)[32],
                                       const float2* tlo, const float2* thi) {
#pragma unroll
    for (int k = 0; k < 16; k++) {
        const int l = sigp(k, N);
        float2 pl = tlo[l];
        float r = sr[k], m = si[k];
        sr[k] = fmaf(pl.x, r, -pl.y * m);
        si[k] = fmaf(pl.x, m, pl.y * r);
        float2 ph = thi[l];
        float r2 = sr[k + 16], m2 = si[k + 16];
        sr[k + 16] = fmaf(ph.x, r2, -ph.y * m2);
        si[k + 16] = fmaf(ph.x, m2, ph.y * r2);
    }
}

#define TPB 128
#define NSM 148
#define BLKS (NSM * 6)  // one full wave at 6 blocks/SM

__global__ void __launch_bounds__(TPB, 6)
sim_k(const float* __restrict__ x, const float* __restrict__ thetas,
      const float* __restrict__ phis, float* __restrict__ out, int P) {
    // Logical-indexed phase tables, shared per block. Layer-2 CU phases
    // cancel in the bilinear (perm survives at compile time). The layer-2
    // RX on wire 1 (bit 8) also cancels: final-sum weight class depends only
    // on parity(bits 4,2,1) -> R^T W conj(R) = (1+tau^2) W, annihilating its
    // cos^2 from S^2 — angle 8 is never read.
    __shared__ float2 sh_t0[16];    // layer-0 CU phase x (-i)^popc init fold
    __shared__ float2 sh_t1lo[16];  // layer-1 CU phase
    __shared__ float2 sh_t1hi[16];  // layer-1 CU phase + CPhase(phi1) fold
    __shared__ float2 sh_ph[2];     // e^{i phi0}, e^{i phi2}

    int tid = threadIdx.x;
    if (tid < 32) {
        int L = tid >> 4, k = tid & 15;
        float pr, pi;
        cu_walk(k, thetas + 4 * L, pr, pi);
        if (L == 0) {
            int pc = __popc(k) & 3;  // fold (-i)^popc(k) from the RX init
            float nr, ni;
            if (pc == 0)      { nr = pr;  ni = pi;  }
            else if (pc == 1) { nr = pi;  ni = -pr; }
            else if (pc == 2) { nr = -pr; ni = -pi; }
            else              { nr = -pi; ni = pr;  }
            sh_t0[k] = make_float2(nr, ni);
        } else {
            sh_t1lo[k] = make_float2(pr, pi);
            float sp, cp;
            __sincosf(phis[1], &sp, &cp);
            if (sig1(k) & 8)  // CPhase acts on logical b-bit AFTER the perm
                sh_t1hi[k] = make_float2(pr * cp - pi * sp, pr * sp + pi * cp);
            else
                sh_t1hi[k] = make_float2(pr, pi);
        }
    } else if (tid == 32) {
        float s, c; __sincosf(phis[0], &s, &c); sh_ph[0] = make_float2(c, s);
    } else if (tid == 33) {
        float s, c; __sincosf(phis[2], &s, &c); sh_ph[1] = make_float2(c, s);
    }
    __syncthreads();

    // Persistent grid-stride loop: exactly one wave resident, 2-3 patches
    // per thread — kills the 2.31-wave quantization tail.
    for (int p = blockIdx.x * TPB + tid; p < P; p += BLKS * TPB) {
        int b = p >> 14;
        int rem = p & 16383;
        int h2 = rem >> 7;
        int w2 = rem & 127;
        const float* xb =
            x + (size_t)b * 196608 + (size_t)h2 * 512 + (size_t)w2 * 2;

        // 6 pixel loads batched (MLP=6); tau = tan(x/2), S = prod cos(x/2).
        float2 c0r0 = *reinterpret_cast<const float2*>(xb);
        float2 c0r1 = *reinterpret_cast<const float2*>(xb + 256);
        float2 c1r0 = *reinterpret_cast<const float2*>(xb + 65536);
        float2 c1r1 = *reinterpret_cast<const float2*>(xb + 65536 + 256);
        float2 c2r0 = *reinterpret_cast<const float2*>(xb + 131072);
        float2 c2r1 = *reinterpret_cast<const float2*>(xb + 131072 + 256);

        float tv[12];
        float S = 1.0f;
        float s_, c_;
        __sincosf(0.5f * c0r0.x, &s_, &c_); tv[0]  = __fdividef(s_, c_); S *= c_;
        __sincosf(0.5f * c0r0.y, &s_, &c_); tv[1]  = __fdividef(s_, c_); S *= c_;
        __sincosf(0.5f * c0r1.x, &s_, &c_); tv[2]  = __fdividef(s_, c_); S *= c_;
        __sincosf(0.5f * c0r1.y, &s_, &c_); tv[3]  = __fdividef(s_, c_); S *= c_;
        __sincosf(0.5f * c1r0.x, &s_, &c_); tv[4]  = __fdividef(s_, c_); S *= c_;
        __sincosf(0.5f * c1r0.y, &s_, &c_); tv[5]  = __fdividef(s_, c_); S *= c_;
        __sincosf(0.5f * c1r1.x, &s_, &c_); tv[6]  = __fdividef(s_, c_); S *= c_;
        __sincosf(0.5f * c1r1.y, &s_, &c_); tv[7]  = __fdividef(s_, c_); S *= c_;
        // angle 8 (c2r0.x) eliminated algebraically — never touched
        __sincosf(0.5f * c2r0.y, &s_, &c_); tv[9]  = __fdividef(s_, c_); S *= c_;
        __sincosf(0.5f * c2r1.x, &s_, &c_); tv[10] = __fdividef(s_, c_); S *= c_;
        __sincosf(0.5f * c2r1.y, &s_, &c_); tv[11] = __fdividef(s_, c_); S *= c_;

        // Slots 0..15 = lo (wire0=0) branch, 16..31 = hi.
        float sr[32], si[32];

        // Init: product state x layer-0 CU phases; slot k holds sig1(k).
        {
            float abt[4] = {1.f, tv[1], tv[0], tv[0] * tv[1]};
            float det[4] = {1.f, tv[3], tv[2], tv[2] * tv[3]};
#pragma unroll
            for (int k = 0; k < 16; k++) {
                float m = abt[k >> 2] * det[k & 3];
                float2 t0 = sh_t0[k];
                sr[k] = m * t0.x;
                si[k] = m * t0.y;
            }
        }

        // Layer-1 RX on wires 2,3,4: commute with the fork's diagonal phase
        // on logical bit 8 -> run ONCE on the shared state.
        rx16_t<4, 1>(sr, si, tv[5]);
        rx16_t<2, 1>(sr, si, tv[6]);
        rx16_t<1, 1>(sr, si, tv[7]);

        // Fork: hi = lo with CPhase(phi0) on logical b=1 amps (sig1(k)&8).
        {
            float2 p0 = sh_ph[0];
#pragma unroll
            for (int k = 0; k < 16; k++) {
                if (sig1(k) & 8) {
                    sr[k + 16] = fmaf(p0.x, sr[k], -p0.y * si[k]);
                    si[k + 16] = fmaf(p0.x, si[k], p0.y * sr[k]);
                } else {
                    sr[k + 16] = sr[k];
                    si[k + 16] = si[k];
                }
            }
        }

        // Remaining layer-1 RX on wire 1 (bit 8), both branches; then the
        // CU phase tables (CPhase(phi1) folded into the hi table).
        rx_t<8, 1>(sr, si, tv[4]);
        cu_tab<1>(sr, si, sh_t1lo, sh_t1hi);

        // Layer 2 (perm sig^2): only the wires-2,3,4 RX survive.
        rx_t<4, 2>(sr, si, tv[9]);
        rx_t<2, 2>(sr, si, tv[10]);
        rx_t<1, 2>(sr, si, tv[11]);

        // Final (virtual perm sig^3): ev~ = A + cos(phi2)*Br + sin(phi2)*Bi.
        float A = 0.f, Br = 0.f, Bi = 0.f;
#pragma unroll
        for (int k = 0; k < 16; k++) {
            const int l = sigp(k, 3);
            float lr = sr[k], li = si[k], hr = sr[k + 16], hm = si[k + 16];
            if (l & 8) {
                Br = fmaf(lr, hr, Br);
                Br = fmaf(li, hm, Br);
                Bi = fmaf(li, hr, Bi);
                Bi = fmaf(-lr, hm, Bi);
            } else {
                A = fmaf(lr, hr, A);
                A = fmaf(li, hm, A);
            }
        }
        float2 p2 = sh_ph[1];
        float ev = A + fmaf(p2.x, Br, p2.y * Bi);
        out[p] = ev * S * S;
    }
}

extern "C" void kernel_launch(void* const* d_in, const int* in_sizes, int n_in,
                              void* d_out, int out_size) {
    const float* x = nullptr;
    const float* thetas = nullptr;
    const float* phis = nullptr;
    for (int i = 0; i < n_in; i++) {
        if (in_sizes[i] == 12) thetas = (const float*)d_in[i];
        else if (in_sizes[i] == 3) phis = (const float*)d_in[i];
        else x = (const float*)d_in[i];
    }
    float* out = (float*)d_out;

    sim_k<<<BLKS, TPB>>>(x, thetas, phis, out, out_size);
}

// round 15
// speedup vs baseline: 1.1604x; 1.1604x over previous
#include <cuda_runtime.h>
#include <cuda_bf16.h>

// ---- constexpr permutation of the per-layer CU block ----
__host__ __device__ constexpr int sig1(int k) {
    int b = (k >> 3) & 1, c = (k >> 2) & 1, d = (k >> 1) & 1, e = k & 1;
    if (b) c ^= 1;
    if (c) d ^= 1;
    if (d) e ^= 1;
    if (e) b ^= 1;
    return b * 8 + c * 4 + d * 2 + e;
}
__host__ __device__ constexpr int sigp(int k, int n) {
    for (int i = 0; i < n; i++) k = sig1(k);
    return k;
}
__host__ __device__ constexpr int isigp(int j, int n) {
    for (int k = 0; k < 16; k++)
        if (sigp(k, n) == j) return k;
    return 0;
}

// Runtime phase walk for basis state k through one layer's 4 CU gates.
// Target 1->0: -i*e = (s, -c); 0->1: -i*conj(e) = (-s, -c); e = e^{i th/2}.
__device__ __forceinline__ void cu_walk(int k, const float* th,
                                        float& pr, float& pi) {
    pr = 1.f; pi = 0.f;
    int b = (k >> 3) & 1, c = (k >> 2) & 1, d = (k >> 1) & 1, e = k & 1;
    float s, cc, fr, fi, nr, ni;
#define CUW(CTRL, TGT, IDX)                                   \
    if (CTRL) {                                               \
        __sincosf(0.5f * th[IDX], &s, &cc);                   \
        fr = (TGT) ? s : -s; fi = -cc;                        \
        nr = pr * fr - pi * fi; ni = pr * fi + pi * fr;       \
        pr = nr; pi = ni; TGT ^= 1;                           \
    }
    CUW(b, c, 0) CUW(c, d, 1) CUW(d, e, 2) CUW(e, b, 3)
#undef CUW
}

// Unnormalized RX (I - i*tau*X) on wire TB, both branches, perm sig^N.
template <int TB, int N>
__device__ __forceinline__ void rx_t(float (&sr)[32], float (&si)[32],
                                     float tau) {
#pragma unroll
    for (int p = 0; p < 16; p++) {
        const int lp = sigp(p, N);
        if (lp & TB) continue;
        const int q = isigp(lp | TB, N);
        {
            float t0r = sr[p], t0i = si[p], t1r = sr[q], t1i = si[q];
            sr[p] = fmaf(tau, t1i, t0r); si[p] = fmaf(-tau, t1r, t0i);
            sr[q] = fmaf(tau, t0i, t1r); si[q] = fmaf(-tau, t0r, t1i);
        }
        {
            float t0r = sr[p + 16], t0i = si[p + 16];
            float t1r = sr[q + 16], t1i = si[q + 16];
            sr[p + 16] = fmaf(tau, t1i, t0r); si[p + 16] = fmaf(-tau, t1r, t0i);
            sr[q + 16] = fmaf(tau, t0i, t1r); si[q + 16] = fmaf(-tau, t0r, t1i);
        }
    }
}

// Same, but on the lo 16 slots only (pre-fork shared state).
template <int TB, int N>
__device__ __forceinline__ void rx16_t(float (&sr)[32], float (&si)[32],
                                       float tau) {
#pragma unroll
    for (int p = 0; p < 16; p++) {
        const int lp = sigp(p, N);
        if (lp & TB) continue;
        const int q = isigp(lp | TB, N);
        float t0r = sr[p], t0i = si[p], t1r = sr[q], t1i = si[q];
        sr[p] = fmaf(tau, t1i, t0r); si[p] = fmaf(-tau, t1r, t0i);
        sr[q] = fmaf(tau, t0i, t1r); si[q] = fmaf(-tau, t0r, t1i);
    }
}

// Bilinear-folded layer-2 RX on wire TB, applied to the HI branch only.
// conj(G) = (1-tau^2)Z + 2 tau Y = [[d, -ie],[ie, -d]], d=1-tau^2, e=2tau:
//   h0' = d h0 - i e h1  -> (d h0r + e h1i,  d h0i - e h1r)
//   h1' = i e h0 - d h1  -> (-e h0i - d h1r, e h0r - d h1i)
template <int TB>
__device__ __forceinline__ void gz_t(float (&sr)[32], float (&si)[32],
                                     float d, float e) {
#pragma unroll
    for (int p = 0; p < 16; p++) {
        const int lp = sigp(p, 2);
        if (lp & TB) continue;
        const int q = isigp(lp | TB, 2);
        float h0r = sr[p + 16], h0i = si[p + 16];
        float h1r = sr[q + 16], h1i = si[q + 16];
        sr[p + 16] = fmaf(d, h0r, e * h1i);
        si[p + 16] = fmaf(d, h0i, -e * h1r);
        sr[q + 16] = fmaf(-d, h1r, -e * h0i);
        si[q + 16] = fmaf(-d, h1i, e * h0r);
    }
}

// Layer-1 CU block = per-slot phase multiply (perm handled by relabeling).
template <int N>
__device__ __forceinline__ void cu_tab(float (&sr)[32], float (&si)[32],
                                       const float2* tlo, const float2* thi) {
#pragma unroll
    for (int k = 0; k < 16; k++) {
        const int l = sigp(k, N);
        float2 pl = tlo[l];
        float r = sr[k], m = si[k];
        sr[k] = fmaf(pl.x, r, -pl.y * m);
        si[k] = fmaf(pl.x, m, pl.y * r);
        float2 ph = thi[l];
        float r2 = sr[k + 16], m2 = si[k + 16];
        sr[k + 16] = fmaf(ph.x, r2, -ph.y * m2);
        si[k + 16] = fmaf(ph.x, m2, ph.y * r2);
    }
}

#define TPB 128

__global__ void __launch_bounds__(TPB, 6)
sim_k(const float* __restrict__ x, const float* __restrict__ thetas,
      const float* __restrict__ phis, float* __restrict__ out) {
    // Layer-2 CU phases cancel in the bilinear; its wire-1 RX folds into S^2
    // (R^T W conj(R) = (1+tau^2) W, weight class = parity(bits 4,2,1)); the
    // remaining three layer-2 RX fold into the bilinear as
    // W = a I + b ZZZ, R^T I conj(R) = (1+tau^2) I,
    // R^T Z conj(R) = (1-tau^2) Z - 2 tau Y per wire.
    __shared__ float2 sh_t0[16];    // layer-0 CU phase x (-i)^popc init fold
    __shared__ float2 sh_t1lo[16];  // layer-1 CU phase
    __shared__ float2 sh_t1hi[16];  // layer-1 CU phase + CPhase(phi1) fold
    __shared__ float2 sh_ph[2];     // e^{i phi0}, e^{i phi2}

    int tid = threadIdx.x;
    if (tid < 32) {
        int L = tid >> 4, k = tid & 15;
        float pr, pi;
        cu_walk(k, thetas + 4 * L, pr, pi);
        if (L == 0) {
            int pc = __popc(k) & 3;  // fold (-i)^popc(k) from the RX init
            float nr, ni;
            if (pc == 0)      { nr = pr;  ni = pi;  }
            else if (pc == 1) { nr = pi;  ni = -pr; }
            else if (pc == 2) { nr = -pr; ni = -pi; }
            else              { nr = -pi; ni = pr;  }
            sh_t0[k] = make_float2(nr, ni);
        } else {
            sh_t1lo[k] = make_float2(pr, pi);
            float sp, cp;
            __sincosf(phis[1], &sp, &cp);
            if (sig1(k) & 8)  // CPhase acts on logical b-bit AFTER the perm
                sh_t1hi[k] = make_float2(pr * cp - pi * sp, pr * sp + pi * cp);
            else
                sh_t1hi[k] = make_float2(pr, pi);
        }
    } else if (tid == 32) {
        float s, c; __sincosf(phis[0], &s, &c); sh_ph[0] = make_float2(c, s);
    } else if (tid == 33) {
        float s, c; __sincosf(phis[2], &s, &c); sh_ph[1] = make_float2(c, s);
    }
    __syncthreads();

    int p = blockIdx.x * TPB + tid;
    int b = p >> 14;
    int rem = p & 16383;
    int h2 = rem >> 7;
    int w2 = rem & 127;
    const float* xb = x + (size_t)b * 196608 + (size_t)h2 * 512 + (size_t)w2 * 2;

    // All 6 pixel loads batched (MLP=6); tau = tan(x/2), S = prod cos(x/2).
    float2 c0r0 = *reinterpret_cast<const float2*>(xb);
    float2 c0r1 = *reinterpret_cast<const float2*>(xb + 256);
    float2 c1r0 = *reinterpret_cast<const float2*>(xb + 65536);
    float2 c1r1 = *reinterpret_cast<const float2*>(xb + 65536 + 256);
    float2 c2r0 = *reinterpret_cast<const float2*>(xb + 131072);
    float2 c2r1 = *reinterpret_cast<const float2*>(xb + 131072 + 256);

    float tv[12];
    float S = 1.0f;
    float s_, c_;
    __sincosf(0.5f * c0r0.x, &s_, &c_); tv[0]  = __fdividef(s_, c_); S *= c_;
    __sincosf(0.5f * c0r0.y, &s_, &c_); tv[1]  = __fdividef(s_, c_); S *= c_;
    __sincosf(0.5f * c0r1.x, &s_, &c_); tv[2]  = __fdividef(s_, c_); S *= c_;
    __sincosf(0.5f * c0r1.y, &s_, &c_); tv[3]  = __fdividef(s_, c_); S *= c_;
    __sincosf(0.5f * c1r0.x, &s_, &c_); tv[4]  = __fdividef(s_, c_); S *= c_;
    __sincosf(0.5f * c1r0.y, &s_, &c_); tv[5]  = __fdividef(s_, c_); S *= c_;
    __sincosf(0.5f * c1r1.x, &s_, &c_); tv[6]  = __fdividef(s_, c_); S *= c_;
    __sincosf(0.5f * c1r1.y, &s_, &c_); tv[7]  = __fdividef(s_, c_); S *= c_;
    // angle 8 (c2r0.x) eliminated algebraically — never touched
    __sincosf(0.5f * c2r0.y, &s_, &c_); tv[9]  = __fdividef(s_, c_); S *= c_;
    __sincosf(0.5f * c2r1.x, &s_, &c_); tv[10] = __fdividef(s_, c_); S *= c_;
    __sincosf(0.5f * c2r1.y, &s_, &c_); tv[11] = __fdividef(s_, c_); S *= c_;

    // Slots 0..15 = lo (wire0=0) branch, 16..31 = hi. ev = S^2 ev~.
    float sr[32], si[32];

    // Init: product state x layer-0 CU phases (m real); slot k holds sig1(k).
    {
        float abt[4] = {1.f, tv[1], tv[0], tv[0] * tv[1]};
        float det[4] = {1.f, tv[3], tv[2], tv[2] * tv[3]};
#pragma unroll
        for (int k = 0; k < 16; k++) {
            float m = abt[k >> 2] * det[k & 3];
            float2 t0 = sh_t0[k];
            sr[k] = m * t0.x;
            si[k] = m * t0.y;
        }
    }

    // Layer-1 RX on wires 2,3,4 (bits 4,2,1): commute with the fork's
    // diagonal phase on logical bit 8 -> run ONCE on the shared state.
    rx16_t<4, 1>(sr, si, tv[5]);
    rx16_t<2, 1>(sr, si, tv[6]);
    rx16_t<1, 1>(sr, si, tv[7]);

    // Fork: hi branch = lo with CPhase(phi0) on logical b=1 amps (sig1(k)&8).
    {
        float2 p0 = sh_ph[0];
#pragma unroll
        for (int k = 0; k < 16; k++) {
            if (sig1(k) & 8) {
                sr[k + 16] = fmaf(p0.x, sr[k], -p0.y * si[k]);
                si[k + 16] = fmaf(p0.x, si[k], p0.y * sr[k]);
            } else {
                sr[k + 16] = sr[k];
                si[k + 16] = si[k];
            }
        }
    }

    // Remaining layer-1 RX on wire 1 (bit 8), both branches; then CU phases
    // (CPhase(phi1) folded into the hi table).
    rx_t<8, 1>(sr, si, tv[4]);
    cu_tab<1>(sr, si, sh_t1lo, sh_t1hi);

    // S1 = sum_k lo_k * conj(hi_k) BEFORE the folded layer-2 rotations.
    float S1r = 0.f, S1i = 0.f;
#pragma unroll
    for (int k = 0; k < 16; k++) {
        float lr = sr[k], li = si[k], hr = sr[k + 16], hm = si[k + 16];
        S1r = fmaf(lr, hr, S1r); S1r = fmaf(li, hm, S1r);
        S1i = fmaf(li, hr, S1i); S1i = fmaf(-lr, hm, S1i);
    }

    // Apply conj(G) per wire to the HI branch only: the folded form of all
    // three layer-2 RX inside the ZZZ term.
    gz_t<4>(sr, si, fmaf(-tv[9],  tv[9],  1.f), 2.f * tv[9]);
    gz_t<2>(sr, si, fmaf(-tv[10], tv[10], 1.f), 2.f * tv[10]);
    gz_t<1>(sr, si, fmaf(-tv[11], tv[11], 1.f), 2.f * tv[11]);

    // S2 = sum_k lo_k * conj(hi'_k).
    float S2r = 0.f, S2i = 0.f;
#pragma unroll
    for (int k = 0; k < 16; k++) {
        float lr = sr[k], li = si[k], hr = sr[k + 16], hm = si[k + 16];
        S2r = fmaf(lr, hr, S2r); S2r = fmaf(li, hm, S2r);
        S2i = fmaf(li, hr, S2i); S2i = fmaf(-lr, hm, S2i);
    }

    // P = prod (1+tau^2); ev~ = Re(a P S1 + b S2),
    // a = (1+e^{-i phi2})/2, b = (1-e^{-i phi2})/2 (conj: hi is conjugated).
    float P = fmaf(tv[9], tv[9], 1.f) * fmaf(tv[10], tv[10], 1.f) *
              fmaf(tv[11], tv[11], 1.f);
    float2 p2 = sh_ph[1];
    float ev = P * (fmaf(p2.x + 1.f, S1r, p2.y * S1i)) +
               fmaf(1.f - p2.x, S2r, -p2.y * S2i);
    out[p] = 0.5f * ev * S * S;
}

extern "C" void kernel_launch(void* const* d_in, const int* in_sizes, int n_in,
                              void* d_out, int out_size) {
    const float* x = nullptr;
    const float* thetas = nullptr;
    const float* phis = nullptr;
    for (int i = 0; i < n_in; i++) {
        if (in_sizes[i] == 12) thetas = (const float*)d_in[i];
        else if (in_sizes[i] == 3) phis = (const float*)d_in[i];
        else x = (const float*)d_in[i];
    }
    float* out = (float*)d_out;

    int grid = (out_size + TPB - 1) / TPB;  // 2048 for P = 262144
    sim_k<<<grid, TPB>>>(x, thetas, phis, out);
}